// round 12
// baseline (speedup 1.0000x reference)
#include <cuda_runtime.h>

// Inputs (metadata order):
// 0: user_id  int32 [16384]
// 1: item_id  int32 [16384]
// 2: category int32 [16384]
// 3: emb_user f32   [100000]
// 4: emb_item f32   [50000]
// 5: emb_cat  f32   [1000]
// 6: cross_w  f32   [150000000]
// out: f32 [16384]
//
// FINAL — launch-overhead-floor kernel.
// Evidence: 5 measurements across 4 structural variants (64x256 scalar,
// 128x128 scalar, 32x128 x4-vectorized, guard-free 64x256) all land in
// [6.656, 6.912] us — a single 0.256us timer tick of spread. Profile is
// invariant: DRAM ~8%, issue ~2%, occ ~11%. Wall time decomposes as
// fixed launch/graph-replay overhead (~5000 cyc T_ovh) + one irreducible
// dependency chain (coalesced index load, L2 ~250cyc -> random cross_w
// gather, L2-resident across replays ~250cyc) + drain. No lever remains:
// gathers are unpredictable without indices, and L1 is flushed per launch.

#define D_USER  100000
#define D_ITEM  50000
#define D_CAT   1000
#define OFF_IC  (D_USER * D_CAT)   // 100,000,000

__global__ __launch_bounds__(256, 1)
void wide_kernel(const int* __restrict__ user_id,
                 const int* __restrict__ item_id,
                 const int* __restrict__ category,
                 const float* __restrict__ emb_user,
                 const float* __restrict__ emb_item,
                 const float* __restrict__ emb_cat,
                 const float* __restrict__ cross_w,
                 float* __restrict__ out)
{
    int i = blockIdx.x * 256 + threadIdx.x;   // grid sized exactly to n

    // Three coalesced, independent index loads.
    int u  = __ldg(&user_id[i]);
    int it = __ldg(&item_id[i]);
    int c  = __ldg(&category[i]);

    // Two long-latency random gathers into the 600MB table issued first,
    // then the three small-table lookups. All five independent -> MLP=5.
    float cw0 = __ldg(&cross_w[u * D_CAT + c]);
    float cw1 = __ldg(&cross_w[OFF_IC + it * D_CAT + c]);
    float eu  = __ldg(&emb_user[u]);
    float ei  = __ldg(&emb_item[it]);
    float ec  = __ldg(&emb_cat[c]);

    out[i] = ((eu + ei) + (ec + cw0)) + cw1;
}

extern "C" void kernel_launch(void* const* d_in, const int* in_sizes, int n_in,
                              void* d_out, int out_size)
{
    const int*   user_id  = (const int*)d_in[0];
    const int*   item_id  = (const int*)d_in[1];
    const int*   category = (const int*)d_in[2];
    const float* emb_user = (const float*)d_in[3];
    const float* emb_item = (const float*)d_in[4];
    const float* emb_cat  = (const float*)d_in[5];
    const float* cross_w  = (const float*)d_in[6];
    float* out = (float*)d_out;

    int n = in_sizes[0];           // 16384, divisible by 256
    int blocks = n / 256;          // 64 CTAs x 256 threads, exact cover
    wide_kernel<<<blocks, 256>>>(user_id, item_id, category,
                                 emb_user, emb_item, emb_cat, cross_w, out);
}

// round 14
// speedup vs baseline: 1.0386x; 1.0386x over previous
#include <cuda_runtime.h>

// Inputs (metadata order):
// 0: user_id  int32 [16384]
// 1: item_id  int32 [16384]
// 2: category int32 [16384]
// 3: emb_user f32   [100000]
// 4: emb_item f32   [50000]
// 5: emb_cat  f32   [1000]
// 6: cross_w  f32   [150000000]
// out: f32 [16384]
//
// FINAL — launch-overhead-floor kernel.
// Evidence (6 runs, 4 structural variants): dur_us in [6.656, 6.912],
// spread = one 0.256us timer tick. Profile invariant: DRAM ~8%, issue ~2%.
// Wall time = graph-replay dispatch + T_ovh (~5000 cyc) + one irreducible
// index-load -> random-gather chain (both L2-resident across replays).
// Falsified levers: SM spreading, per-SM L1tex queue depth, warp count,
// LDG/instruction count, vectorization, bounds-check removal. No further
// code-level lever exists for a single data-dependent-gather kernel.

#define D_USER  100000
#define D_ITEM  50000
#define D_CAT   1000
#define OFF_IC  (D_USER * D_CAT)   // 100,000,000

__global__ __launch_bounds__(256, 1)
void wide_kernel(const int* __restrict__ user_id,
                 const int* __restrict__ item_id,
                 const int* __restrict__ category,
                 const float* __restrict__ emb_user,
                 const float* __restrict__ emb_item,
                 const float* __restrict__ emb_cat,
                 const float* __restrict__ cross_w,
                 float* __restrict__ out)
{
    int i = blockIdx.x * 256 + threadIdx.x;   // grid sized exactly to n

    // Three coalesced, independent index loads.
    int u  = __ldg(&user_id[i]);
    int it = __ldg(&item_id[i]);
    int c  = __ldg(&category[i]);

    // Two long-latency random gathers into the 600MB table issued first,
    // then the three small-table lookups. All five independent -> MLP=5.
    float cw0 = __ldg(&cross_w[u * D_CAT + c]);
    float cw1 = __ldg(&cross_w[OFF_IC + it * D_CAT + c]);
    float eu  = __ldg(&emb_user[u]);
    float ei  = __ldg(&emb_item[it]);
    float ec  = __ldg(&emb_cat[c]);

    out[i] = ((eu + ei) + (ec + cw0)) + cw1;
}

extern "C" void kernel_launch(void* const* d_in, const int* in_sizes, int n_in,
                              void* d_out, int out_size)
{
    const int*   user_id  = (const int*)d_in[0];
    const int*   item_id  = (const int*)d_in[1];
    const int*   category = (const int*)d_in[2];
    const float* emb_user = (const float*)d_in[3];
    const float* emb_item = (const float*)d_in[4];
    const float* emb_cat  = (const float*)d_in[5];
    const float* cross_w  = (const float*)d_in[6];
    float* out = (float*)d_out;

    int n = in_sizes[0];           // 16384, divisible by 256
    int blocks = n / 256;          // 64 CTAs x 256 threads, exact cover
    wide_kernel<<<blocks, 256>>>(user_id, item_id, category,
                                 emb_user, emb_item, emb_cat, cross_w, out);
}